// round 5
// baseline (speedup 1.0000x reference)
#include <cuda_runtime.h>
#include <math.h>
#include <stdint.h>

#define BATCH  2
#define CH     512
#define NPIX   4096      // 64*64
#define GROUPS 32
#define CPG    (CH/GROUPS)   // 16
#define EPS    1e-6f
#define STAGES 3

// ---------------- scratch (device globals; no allocation) ----------------
__device__ float g_hn[(size_t)BATCH*CH*NPIX];
__device__ float g_q [(size_t)BATCH*CH*NPIX];
__device__ float g_k [(size_t)BATCH*CH*NPIX];
__device__ float g_v [(size_t)BATCH*CH*NPIX];
__device__ float g_o [(size_t)BATCH*CH*NPIX];
__device__ float g_s [(size_t)BATCH*NPIX*NPIX];   // exp(scores) (128 MiB)
__device__ float g_S [(size_t)BATCH*NPIX];        // row sums of exp(scores)

// ---------------- GroupNorm ----------------
__global__ void gn_kernel(const float* __restrict__ x,
                          const float* __restrict__ gamma,
                          const float* __restrict__ beta)
{
    const int b = blockIdx.y, g = blockIdx.x;
    const size_t base = ((size_t)b*CH + (size_t)g*CPG) * NPIX;
    const float* xp = x + base;
    float* hp = g_hn + base;
    const int NE = CPG * NPIX; // 65536

    float s = 0.f, ss = 0.f;
    for (int i = threadIdx.x*4; i < NE; i += blockDim.x*4) {
        float4 v = *(const float4*)(xp + i);
        s  += v.x + v.y + v.z + v.w;
        ss += v.x*v.x + v.y*v.y + v.z*v.z + v.w*v.w;
    }
    __shared__ float sh1[256], sh2[256];
    sh1[threadIdx.x] = s; sh2[threadIdx.x] = ss;
    __syncthreads();
    for (int o = 128; o > 0; o >>= 1) {
        if (threadIdx.x < o) {
            sh1[threadIdx.x] += sh1[threadIdx.x + o];
            sh2[threadIdx.x] += sh2[threadIdx.x + o];
        }
        __syncthreads();
    }
    const float mu  = sh1[0] / (float)NE;
    const float var = sh2[0] / (float)NE - mu*mu;
    const float inv = rsqrtf(var + EPS);

    for (int i = threadIdx.x*4; i < NE; i += blockDim.x*4) {
        int c = g*CPG + i / NPIX;
        float ga = gamma[c], be = beta[c];
        float4 v = *(const float4*)(xp + i);
        v.x = (v.x - mu)*inv*ga + be;
        v.y = (v.y - mu)*inv*ga + be;
        v.z = (v.z - mu)*inv*ga + be;
        v.w = (v.w - mu)*inv*ga + be;
        *(float4*)(hp + i) = v;
    }
}

__global__ void zero_S_kernel()
{
    int i = blockIdx.x * blockDim.x + threadIdx.x;
    if (i < BATCH*NPIX) g_S[i] = 0.f;
}

// ---------------- low-level helpers ----------------
__device__ __forceinline__ uint32_t smem_u32(const void* p) {
    return (uint32_t)__cvta_generic_to_shared(p);
}
__device__ __forceinline__ void cp16(uint32_t dst, const float* src) {
    asm volatile("cp.async.cg.shared.global [%0], [%1], 16;" :: "r"(dst), "l"(src));
}
__device__ __forceinline__ void mma_tf32(float* c, const uint32_t* a, const uint32_t* b) {
    asm volatile(
        "mma.sync.aligned.m16n8k8.row.col.f32.tf32.tf32.f32 "
        "{%0,%1,%2,%3}, {%4,%5,%6,%7}, {%8,%9}, {%0,%1,%2,%3};"
        : "+f"(c[0]), "+f"(c[1]), "+f"(c[2]), "+f"(c[3])
        : "r"(a[0]), "r"(a[1]), "r"(a[2]), "r"(a[3]),
          "r"(b[0]), "r"(b[1]));
}
__device__ __forceinline__ uint32_t fb(float x) { return __float_as_uint(x); }

// ---------------- tensor-core tf32 GEMM core ----------------
// C[m,n] = alpha * sum_k Aop[m,k]*Bop[k,n]
// Block tile 128(m) x 256(n), BK=16, 256 threads = 8 warps (2m x 4n),
// warp tile 64x64. 3-stage cp.async pipeline. Raw fp32 bits as tf32.
// AMODE 0: A[K,M] global -> smem As[k][m] pitch 136
// AMODE 1: A[M,K] global -> smem As[m][k] pitch 20
// BMODE 0: B[K,N] global -> Bs[k][n] pitch 264
// BMODE 1: B[N,K] global -> Bs[n][k] pitch 20
#define PA0 136
#define PB0 264
#define P1  20
template<int AMODE, int BMODE, bool BIAS, bool RESID, bool SCORES, bool COLSCALE>
__device__ __forceinline__ void gemm_core(
    const float* __restrict__ A, const float* __restrict__ B,
    float* __restrict__ Cm, const float* __restrict__ bias,
    const float* __restrict__ res, float* __restrict__ rowsum,
    const float* __restrict__ colsum,
    int M, int N, int K, float alpha, int m0, int n0)
{
    constexpr int AW = (AMODE == 0) ? 16*PA0 : 128*P1;   // words per A stage
    constexpr int BW = (BMODE == 0) ? 16*PB0 : 256*P1;
    extern __shared__ float smem[];
    float* Asm = smem;
    float* Bsm = smem + STAGES*AW;

    const int lda = (AMODE == 0) ? M : K;
    const int ldb = (BMODE == 0) ? N : K;

    const int tid  = threadIdx.x;
    const int lane = tid & 31;
    const int warp = tid >> 5;
    const int wm = (warp & 1) * 64;     // m offset (2 warps)
    const int wn = (warp >> 1) * 64;    // n offset (4 warps)
    const int g  = lane >> 2;
    const int tg = lane & 3;

    float acc[4][8][4];
    #pragma unroll
    for (int i = 0; i < 4; i++)
        #pragma unroll
        for (int j = 0; j < 8; j++)
            #pragma unroll
            for (int r = 0; r < 4; r++) acc[i][j][r] = 0.f;

    auto load_tile = [&](int s, int k0) {
        float* Ab = Asm + s*AW;
        float* Bb = Bsm + s*BW;
        if (AMODE == 0) {          // 16 x 128, 512 cp16
            #pragma unroll
            for (int t = 0; t < 2; t++) {
                int idx = tid + t*256;
                int kk = idx >> 5, mseg = (idx & 31) * 4;
                cp16(smem_u32(Ab + kk*PA0 + mseg),
                     A + (size_t)(k0 + kk)*lda + m0 + mseg);
            }
        } else {                   // 128 x 16, 512 cp16
            #pragma unroll
            for (int t = 0; t < 2; t++) {
                int idx = tid + t*256;
                int row = idx >> 2, kseg = (idx & 3) * 4;
                cp16(smem_u32(Ab + row*P1 + kseg),
                     A + (size_t)(m0 + row)*lda + k0 + kseg);
            }
        }
        if (BMODE == 0) {          // 16 x 256, 1024 cp16
            #pragma unroll
            for (int t = 0; t < 4; t++) {
                int idx = tid + t*256;
                int kk = idx >> 6, nseg = (idx & 63) * 4;
                cp16(smem_u32(Bb + kk*PB0 + nseg),
                     B + (size_t)(k0 + kk)*ldb + n0 + nseg);
            }
        } else {                   // 256 x 16, 1024 cp16
            #pragma unroll
            for (int t = 0; t < 4; t++) {
                int idx = tid + t*256;
                int row = idx >> 2, kseg = (idx & 3) * 4;
                cp16(smem_u32(Bb + row*P1 + kseg),
                     B + (size_t)(n0 + row)*ldb + k0 + kseg);
            }
        }
    };

    auto compute = [&](int s) {
        const float* Ab = Asm + s*AW;
        const float* Bb = Bsm + s*BW;
        #pragma unroll
        for (int kk = 0; kk < 16; kk += 8) {
            uint32_t af[4][4];
            #pragma unroll
            for (int mi = 0; mi < 4; mi++) {
                int r = wm + mi*16 + g;
                if (AMODE == 0) {
                    af[mi][0] = fb(Ab[(kk+tg  )*PA0 + r]);
                    af[mi][1] = fb(Ab[(kk+tg  )*PA0 + r + 8]);
                    af[mi][2] = fb(Ab[(kk+tg+4)*PA0 + r]);
                    af[mi][3] = fb(Ab[(kk+tg+4)*PA0 + r + 8]);
                } else {
                    af[mi][0] = fb(Ab[(r    )*P1 + kk+tg]);
                    af[mi][1] = fb(Ab[(r + 8)*P1 + kk+tg]);
                    af[mi][2] = fb(Ab[(r    )*P1 + kk+tg+4]);
                    af[mi][3] = fb(Ab[(r + 8)*P1 + kk+tg+4]);
                }
            }
            #pragma unroll
            for (int ni = 0; ni < 8; ni++) {
                uint32_t bf[2];
                int cl = wn + ni*8 + g;
                if (BMODE == 0) {
                    bf[0] = fb(Bb[(kk+tg  )*PB0 + cl]);
                    bf[1] = fb(Bb[(kk+tg+4)*PB0 + cl]);
                } else {
                    bf[0] = fb(Bb[cl*P1 + kk+tg]);
                    bf[1] = fb(Bb[cl*P1 + kk+tg+4]);
                }
                #pragma unroll
                for (int mi = 0; mi < 4; mi++)
                    mma_tf32(acc[mi][ni], af[mi], bf);
            }
        }
    };

    // ---- 3-stage pipeline ----
    load_tile(0, 0);
    asm volatile("cp.async.commit_group;" ::: "memory");
    load_tile(1, 16);
    asm volatile("cp.async.commit_group;" ::: "memory");

    int rd = 0;
    for (int k0 = 0; k0 < K; k0 += 16) {
        asm volatile("cp.async.wait_group 1;" ::: "memory");
        __syncthreads();
        int kn = k0 + 32;
        if (kn < K) {
            int ws = rd + 2; if (ws >= STAGES) ws -= STAGES;
            load_tile(ws, kn);
        }
        asm volatile("cp.async.commit_group;" ::: "memory");
        compute(rd);
        rd++; if (rd >= STAGES) rd = 0;
    }

    // ---- epilogue ----
    #pragma unroll
    for (int mi = 0; mi < 4; mi++) {
        int row0 = m0 + wm + mi*16 + g;
        int row1 = row0 + 8;
        float b0 = BIAS ? bias[row0] : 0.f;
        float b1 = BIAS ? bias[row1] : 0.f;
        float sum0 = 0.f, sum1 = 0.f;
        #pragma unroll
        for (int ni = 0; ni < 8; ni++) {
            int col = n0 + wn + ni*8 + 2*tg;
            float c0 = acc[mi][ni][0]*alpha;
            float c1 = acc[mi][ni][1]*alpha;
            float c2 = acc[mi][ni][2]*alpha;
            float c3 = acc[mi][ni][3]*alpha;
            if (SCORES) {
                c0 = __expf(c0); c1 = __expf(c1);
                c2 = __expf(c2); c3 = __expf(c3);
                sum0 += c0 + c1;
                sum1 += c2 + c3;
            }
            if (COLSCALE) {
                float i0 = __fdividef(1.f, colsum[col]);
                float i1 = __fdividef(1.f, colsum[col + 1]);
                c0 *= i0; c1 *= i1; c2 *= i0; c3 *= i1;
            }
            c0 += b0; c1 += b0; c2 += b1; c3 += b1;
            if (RESID) {
                c0 += res[(size_t)row0*N + col];
                c1 += res[(size_t)row0*N + col + 1];
                c2 += res[(size_t)row1*N + col];
                c3 += res[(size_t)row1*N + col + 1];
            }
            *(float2*)(Cm + (size_t)row0*N + col) = make_float2(c0, c1);
            *(float2*)(Cm + (size_t)row1*N + col) = make_float2(c2, c3);
        }
        if (SCORES) {
            sum0 += __shfl_xor_sync(0xffffffffu, sum0, 1);
            sum0 += __shfl_xor_sync(0xffffffffu, sum0, 2);
            sum1 += __shfl_xor_sync(0xffffffffu, sum1, 1);
            sum1 += __shfl_xor_sync(0xffffffffu, sum1, 2);
            if (tg == 0) {
                atomicAdd(rowsum + row0, sum0);
                atomicAdd(rowsum + row1, sum1);
            }
        }
    }
}

// ---------------- kernel wrappers ----------------
static const size_t sBC = (size_t)CH * NPIX;
static const size_t sS  = (size_t)NPIX * NPIX;

// smem sizes (bytes)
#define SM_A0 (16*PA0*4)
#define SM_B0 (16*PB0*4)
#define SM_A1 (128*P1*4)
#define SM_B1 (256*P1*4)
#define SMEM_QKV   (STAGES*(SM_A1 + SM_B0))
#define SMEM_SCO   (STAGES*(SM_A0 + SM_B0))
#define SMEM_AV    (STAGES*(SM_A1 + SM_B1))
#define SMEM_OUT   (STAGES*(SM_A1 + SM_B0))

// fused q/k/v: grid (NPIX/256, 3*CH/128, BATCH)
__global__ __launch_bounds__(256, 1)
void qkv_kernel(const float* __restrict__ hn,
                const float* __restrict__ wq, const float* __restrict__ bq,
                const float* __restrict__ wk, const float* __restrict__ bk,
                const float* __restrict__ wv, const float* __restrict__ bv,
                float* __restrict__ q, float* __restrict__ k, float* __restrict__ v)
{
    const int sel = blockIdx.y >> 2;          // 0=q 1=k 2=v (CH/128 = 4)
    const int my  = blockIdx.y & 3;
    const int bz  = blockIdx.z;
    const float* W  = sel == 0 ? wq : sel == 1 ? wk : wv;
    const float* bb = sel == 0 ? bq : sel == 1 ? bk : bv;
    float* C        = sel == 0 ? q  : sel == 1 ? k  : v;
    gemm_core<1, 0, true, false, false, false>(
        W, hn + bz*sBC, C + bz*sBC, bb, nullptr, nullptr, nullptr,
        CH, NPIX, CH, 1.f, my*128, blockIdx.x*256);
}

// scores: e = exp(scale * q^T k). grid (NPIX/256, NPIX/128, BATCH)
__global__ __launch_bounds__(256, 1)
void scores_kernel(const float* __restrict__ q, const float* __restrict__ k,
                   float scale)
{
    const int bz = blockIdx.z;
    gemm_core<0, 0, false, false, true, false>(
        q + bz*sBC, k + bz*sBC, g_s + bz*sS, nullptr, nullptr,
        g_S + bz*NPIX, nullptr,
        NPIX, NPIX, CH, scale, blockIdx.y*128, blockIdx.x*256);
}

// o_un = v * e^T. grid (NPIX/256, CH/128, BATCH)
__global__ __launch_bounds__(256, 1)
void av_kernel(const float* __restrict__ v)
{
    const int bz = blockIdx.z;
    gemm_core<1, 1, false, false, false, false>(
        v + bz*sBC, g_s + bz*sS, g_o + bz*sBC, nullptr, nullptr, nullptr, nullptr,
        CH, NPIX, NPIX, 1.f, blockIdx.y*128, blockIdx.x*256);
}

// out = (wo * o_un)/S + bo + x. grid (NPIX/256, CH/128, BATCH)
__global__ __launch_bounds__(256, 1)
void outconv_kernel(const float* __restrict__ wo, const float* __restrict__ bo,
                    const float* __restrict__ x, float* __restrict__ out)
{
    const int bz = blockIdx.z;
    gemm_core<1, 0, true, true, false, true>(
        wo, g_o + bz*sBC, out + bz*sBC, bo, x + bz*sBC, nullptr, g_S + bz*NPIX,
        CH, NPIX, CH, 1.f, blockIdx.y*128, blockIdx.x*256);
}

// ---------------- launch ----------------
extern "C" void kernel_launch(void* const* d_in, const int* in_sizes, int n_in,
                              void* d_out, int out_size)
{
    const float* x     = (const float*)d_in[0];
    const float* gamma = (const float*)d_in[1];
    const float* beta  = (const float*)d_in[2];
    const float* wq    = (const float*)d_in[3];
    const float* bq    = (const float*)d_in[4];
    const float* wk    = (const float*)d_in[5];
    const float* bk    = (const float*)d_in[6];
    const float* wv    = (const float*)d_in[7];
    const float* bv    = (const float*)d_in[8];
    const float* wo    = (const float*)d_in[9];
    const float* bo    = (const float*)d_in[10];
    float* out = (float*)d_out;

    float *p_hn, *p_q, *p_k, *p_v;
    cudaGetSymbolAddress((void**)&p_hn, g_hn);
    cudaGetSymbolAddress((void**)&p_q,  g_q);
    cudaGetSymbolAddress((void**)&p_k,  g_k);
    cudaGetSymbolAddress((void**)&p_v,  g_v);

    cudaFuncSetAttribute(qkv_kernel,    cudaFuncAttributeMaxDynamicSharedMemorySize, SMEM_QKV);
    cudaFuncSetAttribute(scores_kernel, cudaFuncAttributeMaxDynamicSharedMemorySize, SMEM_SCO);
    cudaFuncSetAttribute(av_kernel,     cudaFuncAttributeMaxDynamicSharedMemorySize, SMEM_AV);
    cudaFuncSetAttribute(outconv_kernel,cudaFuncAttributeMaxDynamicSharedMemorySize, SMEM_OUT);

    const float scale = rsqrtf((float)CH);

    // 1. GroupNorm + zero row sums
    gn_kernel<<<dim3(GROUPS, BATCH), 256>>>(x, gamma, beta);
    zero_S_kernel<<<(BATCH*NPIX + 255)/256, 256>>>();

    // 2. fused q/k/v
    qkv_kernel<<<dim3(NPIX/256, 3*(CH/128), BATCH), 256, SMEM_QKV>>>(
        p_hn, wq, bq, wk, bk, wv, bv, p_q, p_k, p_v);

    // 3. e = exp(scale * q^T k), row sums via atomics
    scores_kernel<<<dim3(NPIX/256, NPIX/128, BATCH), 256, SMEM_SCO>>>(p_q, p_k, scale);

    // 4. o_un = v * e^T
    av_kernel<<<dim3(NPIX/256, CH/128, BATCH), 256, SMEM_AV>>>(p_v);

    // 5. out = (wo * o_un)/S + bo + x
    outconv_kernel<<<dim3(NPIX/256, CH/128, BATCH), 256, SMEM_OUT>>>(wo, bo, x, out);
}

// round 6
// speedup vs baseline: 1.0736x; 1.0736x over previous
#include <cuda_runtime.h>
#include <math.h>
#include <stdint.h>

#define BATCH  2
#define CH     512
#define NPIX   4096      // 64*64
#define GROUPS 32
#define CPG    (CH/GROUPS)   // 16
#define EPS    1e-6f
#define STAGES 4

// ---------------- scratch (device globals; no allocation) ----------------
__device__ float g_hn[(size_t)BATCH*CH*NPIX];
__device__ float g_q [(size_t)BATCH*CH*NPIX];
__device__ float g_k [(size_t)BATCH*CH*NPIX];
__device__ float g_v [(size_t)BATCH*CH*NPIX];
__device__ float g_o [(size_t)BATCH*CH*NPIX];
__device__ float g_s [(size_t)BATCH*NPIX*NPIX];   // exp(scores) (128 MiB)
__device__ float g_S [(size_t)BATCH*NPIX];        // row sums of exp(scores)

// ---------------- GroupNorm ----------------
__global__ void gn_kernel(const float* __restrict__ x,
                          const float* __restrict__ gamma,
                          const float* __restrict__ beta)
{
    const int b = blockIdx.y, g = blockIdx.x;
    const size_t base = ((size_t)b*CH + (size_t)g*CPG) * NPIX;
    const float* xp = x + base;
    float* hp = g_hn + base;
    const int NE = CPG * NPIX; // 65536

    float s = 0.f, ss = 0.f;
    for (int i = threadIdx.x*4; i < NE; i += blockDim.x*4) {
        float4 v = *(const float4*)(xp + i);
        s  += v.x + v.y + v.z + v.w;
        ss += v.x*v.x + v.y*v.y + v.z*v.z + v.w*v.w;
    }
    __shared__ float sh1[256], sh2[256];
    sh1[threadIdx.x] = s; sh2[threadIdx.x] = ss;
    __syncthreads();
    for (int o = 128; o > 0; o >>= 1) {
        if (threadIdx.x < o) {
            sh1[threadIdx.x] += sh1[threadIdx.x + o];
            sh2[threadIdx.x] += sh2[threadIdx.x + o];
        }
        __syncthreads();
    }
    const float mu  = sh1[0] / (float)NE;
    const float var = sh2[0] / (float)NE - mu*mu;
    const float inv = rsqrtf(var + EPS);

    for (int i = threadIdx.x*4; i < NE; i += blockDim.x*4) {
        int c = g*CPG + i / NPIX;
        float ga = gamma[c], be = beta[c];
        float4 v = *(const float4*)(xp + i);
        v.x = (v.x - mu)*inv*ga + be;
        v.y = (v.y - mu)*inv*ga + be;
        v.z = (v.z - mu)*inv*ga + be;
        v.w = (v.w - mu)*inv*ga + be;
        *(float4*)(hp + i) = v;
    }
}

__global__ void zero_S_kernel()
{
    int i = blockIdx.x * blockDim.x + threadIdx.x;
    if (i < BATCH*NPIX) g_S[i] = 0.f;
}

// ---------------- low-level helpers ----------------
__device__ __forceinline__ uint32_t smem_u32(const void* p) {
    return (uint32_t)__cvta_generic_to_shared(p);
}
__device__ __forceinline__ void cp16(uint32_t dst, const float* src) {
    asm volatile("cp.async.cg.shared.global [%0], [%1], 16;" :: "r"(dst), "l"(src));
}
__device__ __forceinline__ void mma_tf32(float* c, const uint32_t* a, const uint32_t* b) {
    asm volatile(
        "mma.sync.aligned.m16n8k8.row.col.f32.tf32.tf32.f32 "
        "{%0,%1,%2,%3}, {%4,%5,%6,%7}, {%8,%9}, {%0,%1,%2,%3};"
        : "+f"(c[0]), "+f"(c[1]), "+f"(c[2]), "+f"(c[3])
        : "r"(a[0]), "r"(a[1]), "r"(a[2]), "r"(a[3]),
          "r"(b[0]), "r"(b[1]));
}
__device__ __forceinline__ uint32_t fb(float x) { return __float_as_uint(x); }

// ---------------- tensor-core tf32 GEMM core ----------------
// C[m,n] = alpha * sum_k Aop[m,k]*Bop[k,n]
// Block tile 128x128, BK=16, 128 threads = 4 warps (2m x 2n),
// warp tile 64x64. 4-stage cp.async pipeline, 2 CTAs/SM.
// AMODE 0: A[K,M] global -> smem As[k][m] pitch 136
// AMODE 1: A[M,K] global -> smem As[m][k] pitch 20
// BMODE 0: B[K,N] global -> Bs[k][n] pitch 136
// BMODE 1: B[N,K] global -> Bs[n][k] pitch 20
#define P0  136
#define P1  20
template<int AMODE, int BMODE, bool BIAS, bool RESID, bool SCORES, bool COLSCALE>
__device__ __forceinline__ void gemm_core(
    const float* __restrict__ A, const float* __restrict__ B,
    float* __restrict__ Cm, const float* __restrict__ bias,
    const float* __restrict__ res, float* __restrict__ rowsum,
    const float* __restrict__ colsum,
    int M, int N, int K, float alpha, int m0, int n0)
{
    constexpr int AW = (AMODE == 0) ? 16*P0 : 128*P1;   // words per A stage
    constexpr int BW = (BMODE == 0) ? 16*P0 : 128*P1;
    extern __shared__ float smem[];
    float* Asm = smem;
    float* Bsm = smem + STAGES*AW;

    const int lda = (AMODE == 0) ? M : K;
    const int ldb = (BMODE == 0) ? N : K;

    const int tid  = threadIdx.x;
    const int lane = tid & 31;
    const int warp = tid >> 5;          // 0..3
    const int wm = (warp & 1) * 64;     // m offset (2 warps)
    const int wn = (warp >> 1) * 64;    // n offset (2 warps)
    const int g  = lane >> 2;
    const int tg = lane & 3;

    float acc[4][8][4];
    #pragma unroll
    for (int i = 0; i < 4; i++)
        #pragma unroll
        for (int j = 0; j < 8; j++)
            #pragma unroll
            for (int r = 0; r < 4; r++) acc[i][j][r] = 0.f;

    auto load_tile = [&](int s, int k0) {
        float* Ab = Asm + s*AW;
        float* Bb = Bsm + s*BW;
        if (AMODE == 0) {          // 16 x 128 tile, 512 float4, 4/thread
            #pragma unroll
            for (int t = 0; t < 4; t++) {
                int idx = tid + t*128;
                int kk = idx >> 5, mseg = (idx & 31) * 4;
                cp16(smem_u32(Ab + kk*P0 + mseg),
                     A + (size_t)(k0 + kk)*lda + m0 + mseg);
            }
        } else {                   // 128 x 16 tile
            #pragma unroll
            for (int t = 0; t < 4; t++) {
                int idx = tid + t*128;
                int row = idx >> 2, kseg = (idx & 3) * 4;
                cp16(smem_u32(Ab + row*P1 + kseg),
                     A + (size_t)(m0 + row)*lda + k0 + kseg);
            }
        }
        if (BMODE == 0) {
            #pragma unroll
            for (int t = 0; t < 4; t++) {
                int idx = tid + t*128;
                int kk = idx >> 5, nseg = (idx & 31) * 4;
                cp16(smem_u32(Bb + kk*P0 + nseg),
                     B + (size_t)(k0 + kk)*ldb + n0 + nseg);
            }
        } else {
            #pragma unroll
            for (int t = 0; t < 4; t++) {
                int idx = tid + t*128;
                int row = idx >> 2, kseg = (idx & 3) * 4;
                cp16(smem_u32(Bb + row*P1 + kseg),
                     B + (size_t)(n0 + row)*ldb + k0 + kseg);
            }
        }
    };

    auto compute = [&](int s) {
        const float* Ab = Asm + s*AW;
        const float* Bb = Bsm + s*BW;
        #pragma unroll
        for (int kk = 0; kk < 16; kk += 8) {
            uint32_t af[4][4];
            #pragma unroll
            for (int mi = 0; mi < 4; mi++) {
                int r = wm + mi*16 + g;
                if (AMODE == 0) {
                    af[mi][0] = fb(Ab[(kk+tg  )*P0 + r]);
                    af[mi][1] = fb(Ab[(kk+tg  )*P0 + r + 8]);
                    af[mi][2] = fb(Ab[(kk+tg+4)*P0 + r]);
                    af[mi][3] = fb(Ab[(kk+tg+4)*P0 + r + 8]);
                } else {
                    af[mi][0] = fb(Ab[(r    )*P1 + kk+tg]);
                    af[mi][1] = fb(Ab[(r + 8)*P1 + kk+tg]);
                    af[mi][2] = fb(Ab[(r    )*P1 + kk+tg+4]);
                    af[mi][3] = fb(Ab[(r + 8)*P1 + kk+tg+4]);
                }
            }
            #pragma unroll
            for (int ni = 0; ni < 8; ni++) {
                uint32_t bf[2];
                int cl = wn + ni*8 + g;
                if (BMODE == 0) {
                    bf[0] = fb(Bb[(kk+tg  )*P0 + cl]);
                    bf[1] = fb(Bb[(kk+tg+4)*P0 + cl]);
                } else {
                    bf[0] = fb(Bb[cl*P1 + kk+tg]);
                    bf[1] = fb(Bb[cl*P1 + kk+tg+4]);
                }
                #pragma unroll
                for (int mi = 0; mi < 4; mi++)
                    mma_tf32(acc[mi][ni], af[mi], bf);
            }
        }
    };

    // ---- 4-stage pipeline: prefetch 3, keep 2 outstanding at compute ----
    load_tile(0, 0);
    asm volatile("cp.async.commit_group;" ::: "memory");
    load_tile(1, 16);
    asm volatile("cp.async.commit_group;" ::: "memory");
    load_tile(2, 32);
    asm volatile("cp.async.commit_group;" ::: "memory");

    int rd = 0;
    for (int k0 = 0; k0 < K; k0 += 16) {
        asm volatile("cp.async.wait_group 2;" ::: "memory");
        __syncthreads();
        int kn = k0 + 48;
        if (kn < K) {
            int ws = rd + 3; if (ws >= STAGES) ws -= STAGES;
            load_tile(ws, kn);
        }
        asm volatile("cp.async.commit_group;" ::: "memory");
        compute(rd);
        rd++; if (rd >= STAGES) rd = 0;
    }

    // ---- epilogue ----
    #pragma unroll
    for (int mi = 0; mi < 4; mi++) {
        int row0 = m0 + wm + mi*16 + g;
        int row1 = row0 + 8;
        float b0 = BIAS ? bias[row0] : 0.f;
        float b1 = BIAS ? bias[row1] : 0.f;
        float sum0 = 0.f, sum1 = 0.f;
        #pragma unroll
        for (int ni = 0; ni < 8; ni++) {
            int col = n0 + wn + ni*8 + 2*tg;
            float c0 = acc[mi][ni][0]*alpha;
            float c1 = acc[mi][ni][1]*alpha;
            float c2 = acc[mi][ni][2]*alpha;
            float c3 = acc[mi][ni][3]*alpha;
            if (SCORES) {
                c0 = __expf(c0); c1 = __expf(c1);
                c2 = __expf(c2); c3 = __expf(c3);
                sum0 += c0 + c1;
                sum1 += c2 + c3;
            }
            if (COLSCALE) {
                float i0 = __fdividef(1.f, colsum[col]);
                float i1 = __fdividef(1.f, colsum[col + 1]);
                c0 *= i0; c1 *= i1; c2 *= i0; c3 *= i1;
            }
            c0 += b0; c1 += b0; c2 += b1; c3 += b1;
            if (RESID) {
                c0 += res[(size_t)row0*N + col];
                c1 += res[(size_t)row0*N + col + 1];
                c2 += res[(size_t)row1*N + col];
                c3 += res[(size_t)row1*N + col + 1];
            }
            *(float2*)(Cm + (size_t)row0*N + col) = make_float2(c0, c1);
            *(float2*)(Cm + (size_t)row1*N + col) = make_float2(c2, c3);
        }
        if (SCORES) {
            sum0 += __shfl_xor_sync(0xffffffffu, sum0, 1);
            sum0 += __shfl_xor_sync(0xffffffffu, sum0, 2);
            sum1 += __shfl_xor_sync(0xffffffffu, sum1, 1);
            sum1 += __shfl_xor_sync(0xffffffffu, sum1, 2);
            if (tg == 0) {
                atomicAdd(rowsum + row0, sum0);
                atomicAdd(rowsum + row1, sum1);
            }
        }
    }
}

// ---------------- kernel wrappers ----------------
static const size_t sBC = (size_t)CH * NPIX;
static const size_t sS  = (size_t)NPIX * NPIX;

// smem sizes (bytes)
#define SM_T0 (16*P0*4)
#define SM_T1 (128*P1*4)
#define SMEM_QKV   (STAGES*(SM_T1 + SM_T0))
#define SMEM_SCO   (STAGES*(SM_T0 + SM_T0))
#define SMEM_AV    (STAGES*(SM_T1 + SM_T1))
#define SMEM_OUT   (STAGES*(SM_T1 + SM_T0))

// fused q/k/v: grid (NPIX/128, 3*CH/128, BATCH)
__global__ __launch_bounds__(128, 2)
void qkv_kernel(const float* __restrict__ hn,
                const float* __restrict__ wq, const float* __restrict__ bq,
                const float* __restrict__ wk, const float* __restrict__ bk,
                const float* __restrict__ wv, const float* __restrict__ bv,
                float* __restrict__ q, float* __restrict__ k, float* __restrict__ v)
{
    const int sel = blockIdx.y >> 2;          // 0=q 1=k 2=v (CH/128 = 4)
    const int my  = blockIdx.y & 3;
    const int bz  = blockIdx.z;
    const float* W  = sel == 0 ? wq : sel == 1 ? wk : wv;
    const float* bb = sel == 0 ? bq : sel == 1 ? bk : bv;
    float* C        = sel == 0 ? q  : sel == 1 ? k  : v;
    gemm_core<1, 0, true, false, false, false>(
        W, hn + bz*sBC, C + bz*sBC, bb, nullptr, nullptr, nullptr,
        CH, NPIX, CH, 1.f, my*128, blockIdx.x*128);
}

// scores: e = exp(scale * q^T k). grid (NPIX/128, NPIX/128, BATCH)
__global__ __launch_bounds__(128, 2)
void scores_kernel(const float* __restrict__ q, const float* __restrict__ k,
                   float scale)
{
    const int bz = blockIdx.z;
    gemm_core<0, 0, false, false, true, false>(
        q + bz*sBC, k + bz*sBC, g_s + bz*sS, nullptr, nullptr,
        g_S + bz*NPIX, nullptr,
        NPIX, NPIX, CH, scale, blockIdx.y*128, blockIdx.x*128);
}

// o_un = v * e^T. grid (NPIX/128, CH/128, BATCH)
__global__ __launch_bounds__(128, 2)
void av_kernel(const float* __restrict__ v)
{
    const int bz = blockIdx.z;
    gemm_core<1, 1, false, false, false, false>(
        v + bz*sBC, g_s + bz*sS, g_o + bz*sBC, nullptr, nullptr, nullptr, nullptr,
        CH, NPIX, NPIX, 1.f, blockIdx.y*128, blockIdx.x*128);
}

// out = (wo * o_un)/S + bo + x. grid (NPIX/128, CH/128, BATCH)
__global__ __launch_bounds__(128, 2)
void outconv_kernel(const float* __restrict__ wo, const float* __restrict__ bo,
                    const float* __restrict__ x, float* __restrict__ out)
{
    const int bz = blockIdx.z;
    gemm_core<1, 0, true, true, false, true>(
        wo, g_o + bz*sBC, out + bz*sBC, bo, x + bz*sBC, nullptr, g_S + bz*NPIX,
        CH, NPIX, CH, 1.f, blockIdx.y*128, blockIdx.x*128);
}

// ---------------- launch ----------------
extern "C" void kernel_launch(void* const* d_in, const int* in_sizes, int n_in,
                              void* d_out, int out_size)
{
    const float* x     = (const float*)d_in[0];
    const float* gamma = (const float*)d_in[1];
    const float* beta  = (const float*)d_in[2];
    const float* wq    = (const float*)d_in[3];
    const float* bq    = (const float*)d_in[4];
    const float* wk    = (const float*)d_in[5];
    const float* bk    = (const float*)d_in[6];
    const float* wv    = (const float*)d_in[7];
    const float* bv    = (const float*)d_in[8];
    const float* wo    = (const float*)d_in[9];
    const float* bo    = (const float*)d_in[10];
    float* out = (float*)d_out;

    float *p_hn, *p_q, *p_k, *p_v;
    cudaGetSymbolAddress((void**)&p_hn, g_hn);
    cudaGetSymbolAddress((void**)&p_q,  g_q);
    cudaGetSymbolAddress((void**)&p_k,  g_k);
    cudaGetSymbolAddress((void**)&p_v,  g_v);

    cudaFuncSetAttribute(qkv_kernel,    cudaFuncAttributeMaxDynamicSharedMemorySize, SMEM_QKV);
    cudaFuncSetAttribute(scores_kernel, cudaFuncAttributeMaxDynamicSharedMemorySize, SMEM_SCO);
    cudaFuncSetAttribute(av_kernel,     cudaFuncAttributeMaxDynamicSharedMemorySize, SMEM_AV);
    cudaFuncSetAttribute(outconv_kernel,cudaFuncAttributeMaxDynamicSharedMemorySize, SMEM_OUT);

    const float scale = rsqrtf((float)CH);

    // 1. GroupNorm + zero row sums
    gn_kernel<<<dim3(GROUPS, BATCH), 256>>>(x, gamma, beta);
    zero_S_kernel<<<(BATCH*NPIX + 255)/256, 256>>>();

    // 2. fused q/k/v
    qkv_kernel<<<dim3(NPIX/128, 3*(CH/128), BATCH), 128, SMEM_QKV>>>(
        p_hn, wq, bq, wk, bk, wv, bv, p_q, p_k, p_v);

    // 3. e = exp(scale * q^T k), row sums via atomics
    scores_kernel<<<dim3(NPIX/128, NPIX/128, BATCH), 128, SMEM_SCO>>>(p_q, p_k, scale);

    // 4. o_un = v * e^T
    av_kernel<<<dim3(NPIX/128, CH/128, BATCH), 128, SMEM_AV>>>(p_v);

    // 5. out = (wo * o_un)/S + bo + x
    outconv_kernel<<<dim3(NPIX/128, CH/128, BATCH), 128, SMEM_OUT>>>(wo, bo, x, out);
}

// round 8
// speedup vs baseline: 1.7443x; 1.6248x over previous
#include <cuda_runtime.h>
#include <cuda_fp16.h>
#include <math.h>
#include <stdint.h>

#define BATCH  2
#define CH     512
#define NPIX   4096
#define GROUPS 32
#define CPG    16
#define EPS    1e-6f
#define STAGES 4
#define BK     32
#define PIT    40        // smem row pitch in halfs
#define PW     20        // pitch in 32-bit words
#define STAGE_HALFS (128*PIT)

// ---------------- scratch (device globals; no allocation) ----------------
__device__ __align__(256) __half g_hnT[(size_t)BATCH*NPIX*CH];  // [pix][ch]
__device__ __align__(256) __half g_qT [(size_t)BATCH*NPIX*CH];  // [pix][ch]
__device__ __align__(256) __half g_kT [(size_t)BATCH*NPIX*CH];  // [pix][ch]
__device__ __align__(256) __half g_v  [(size_t)BATCH*CH*NPIX];  // [ch][pix]
__device__ __align__(256) __half g_e  [(size_t)BATCH*NPIX*NPIX];// [i][j]
__device__ __align__(256) __half g_oT [(size_t)BATCH*NPIX*CH];  // [i][ch]
__device__ __align__(256) __half g_wh [(size_t)4*CH*CH];        // wq|wk|wv|wo fp16
__device__ float g_S  [(size_t)BATCH*NPIX];                     // row sums (fp32)
__device__ float g_stat[(size_t)BATCH*GROUPS*2];                // mu, inv

// ---------------- GroupNorm stats ----------------
__global__ void gn_stats_kernel(const float* __restrict__ x)
{
    const int b = blockIdx.y, g = blockIdx.x;
    const size_t base = ((size_t)b*CH + (size_t)g*CPG) * NPIX;
    const float* xp = x + base;
    const int NE = CPG * NPIX;

    float s = 0.f, ss = 0.f;
    for (int i = threadIdx.x*4; i < NE; i += blockDim.x*4) {
        float4 v = *(const float4*)(xp + i);
        s  += v.x + v.y + v.z + v.w;
        ss += v.x*v.x + v.y*v.y + v.z*v.z + v.w*v.w;
    }
    __shared__ float sh1[256], sh2[256];
    sh1[threadIdx.x] = s; sh2[threadIdx.x] = ss;
    __syncthreads();
    for (int o = 128; o > 0; o >>= 1) {
        if (threadIdx.x < o) {
            sh1[threadIdx.x] += sh1[threadIdx.x + o];
            sh2[threadIdx.x] += sh2[threadIdx.x + o];
        }
        __syncthreads();
    }
    if (threadIdx.x == 0) {
        float mu  = sh1[0] / (float)NE;
        float var = sh2[0] / (float)NE - mu*mu;
        g_stat[(b*GROUPS + g)*2 + 0] = mu;
        g_stat[(b*GROUPS + g)*2 + 1] = rsqrtf(var + EPS);
    }
}

// ---------------- transpose + normalize -> hnT fp16 [pix][ch] ----------------
__global__ void tnorm_kernel(const float* __restrict__ x,
                             const float* __restrict__ gamma,
                             const float* __restrict__ beta)
{
    __shared__ float t[32][33];
    const int p0 = blockIdx.x*32, c0 = blockIdx.y*32, b = blockIdx.z;
    const float* xb = x + (size_t)b*CH*NPIX;
    __half* hb = g_hnT + (size_t)b*NPIX*CH;

    #pragma unroll
    for (int r = 0; r < 4; r++) {
        int c = c0 + threadIdx.y + r*8;
        float mu  = g_stat[(b*GROUPS + (c>>4))*2 + 0];
        float inv = g_stat[(b*GROUPS + (c>>4))*2 + 1];
        float v = xb[(size_t)c*NPIX + p0 + threadIdx.x];
        t[threadIdx.y + r*8][threadIdx.x] = (v - mu)*inv*gamma[c] + beta[c];
    }
    __syncthreads();
    #pragma unroll
    for (int r = 0; r < 4; r++) {
        int p = p0 + threadIdx.y + r*8;
        hb[(size_t)p*CH + c0 + threadIdx.x] = __float2half(t[threadIdx.x][threadIdx.y + r*8]);
    }
}

// ---------------- weight fp32 -> fp16 ----------------
__global__ void cvt_w_kernel(const float* __restrict__ wq, const float* __restrict__ wk,
                             const float* __restrict__ wv, const float* __restrict__ wo)
{
    int i = blockIdx.x * blockDim.x + threadIdx.x;
    const int per = CH*CH;
    if (i >= 4*per) return;
    int m = i / per, off = i - m*per;
    const float* s = (m == 0) ? wq : (m == 1) ? wk : (m == 2) ? wv : wo;
    g_wh[i] = __float2half(s[off]);
}

__global__ void zero_S_kernel()
{
    int i = blockIdx.x * blockDim.x + threadIdx.x;
    if (i < BATCH*NPIX) g_S[i] = 0.f;
}

// ---------------- low-level helpers ----------------
__device__ __forceinline__ uint32_t smem_u32(const void* p) {
    return (uint32_t)__cvta_generic_to_shared(p);
}
__device__ __forceinline__ void cp16(uint32_t dst, const __half* src) {
    asm volatile("cp.async.cg.shared.global [%0], [%1], 16;" :: "r"(dst), "l"(src));
}
__device__ __forceinline__ void mma_f16(float* c, const uint32_t* a, const uint32_t* b) {
    asm volatile(
        "mma.sync.aligned.m16n8k16.row.col.f32.f16.f16.f32 "
        "{%0,%1,%2,%3}, {%4,%5,%6,%7}, {%8,%9}, {%0,%1,%2,%3};"
        : "+f"(c[0]), "+f"(c[1]), "+f"(c[2]), "+f"(c[3])
        : "r"(a[0]), "r"(a[1]), "r"(a[2]), "r"(a[3]),
          "r"(b[0]), "r"(b[1]));
}

// ---------------- fp16 tensor-core GEMM core ----------------
// C[m,n] = alpha * sum_k A[m,k]*B[n,k]; A global [M][K] halfs, B global [N][K].
// Block tile 128x128, BK=32, 128 threads = 4 warps (2m x 2n), warp tile 64x64.
// 4-stage cp.async pipeline, 2 CTAs/SM.
#define SMEM_BYTES (STAGES * STAGE_HALFS * 2 * 2)   // A+B stages, 2B/half
template<bool BIASROW, bool BIASCOL, bool RESID, bool SCORES, bool COLSCALE, bool OUTHALF>
__device__ __forceinline__ void gemm_core(
    const __half* __restrict__ A, const __half* __restrict__ B,
    void* __restrict__ Cv,
    const float* __restrict__ biasR, const float* __restrict__ biasC,
    const float* __restrict__ res,
    float* __restrict__ rowsum, const float* __restrict__ colsum,
    int K, int ldc, float alpha, int m0, int n0)
{
    extern __shared__ __align__(16) char smem_raw[];
    __half* Asm = (__half*)smem_raw;
    __half* Bsm = Asm + STAGES*STAGE_HALFS;

    const int tid  = threadIdx.x;
    const int lane = tid & 31;
    const int warp = tid >> 5;
    const int wm = (warp & 1) * 64;
    const int wn = (warp >> 1) * 64;
    const int g  = lane >> 2;
    const int tg = lane & 3;

    float acc[4][8][4];
    #pragma unroll
    for (int i = 0; i < 4; i++)
        #pragma unroll
        for (int j = 0; j < 8; j++)
            #pragma unroll
            for (int r = 0; r < 4; r++) acc[i][j][r] = 0.f;

    auto load_tile = [&](int s, int k0) {
        __half* Ab = Asm + s*STAGE_HALFS;
        __half* Bb = Bsm + s*STAGE_HALFS;
        #pragma unroll
        for (int t = 0; t < 4; t++) {
            int idx = tid + t*128;
            int row = idx >> 2, seg = (idx & 3) * 8;     // 8 halfs = 16B
            cp16(smem_u32(Ab + row*PIT + seg), A + (size_t)(m0 + row)*K + k0 + seg);
            cp16(smem_u32(Bb + row*PIT + seg), B + (size_t)(n0 + row)*K + k0 + seg);
        }
    };

    auto compute = [&](int s) {
        const uint32_t* Aw = (const uint32_t*)(Asm + s*STAGE_HALFS);
        const uint32_t* Bw = (const uint32_t*)(Bsm + s*STAGE_HALFS);
        #pragma unroll
        for (int kk2 = 0; kk2 < 2; kk2++) {            // k = kk2*16
            const int base = kk2*8 + tg;
            uint32_t af[4][4];
            #pragma unroll
            for (int mi = 0; mi < 4; mi++) {
                int r = wm + mi*16 + g;
                af[mi][0] = Aw[(r    )*PW + base];
                af[mi][1] = Aw[(r + 8)*PW + base];
                af[mi][2] = Aw[(r    )*PW + base + 4];
                af[mi][3] = Aw[(r + 8)*PW + base + 4];
            }
            #pragma unroll
            for (int ni = 0; ni < 8; ni++) {
                int cl = wn + ni*8 + g;
                uint32_t bf[2];
                bf[0] = Bw[cl*PW + base];
                bf[1] = Bw[cl*PW + base + 4];
                #pragma unroll
                for (int mi = 0; mi < 4; mi++)
                    mma_f16(acc[mi][ni], af[mi], bf);
            }
        }
    };

    // ---- 4-stage pipeline ----
    load_tile(0, 0);
    asm volatile("cp.async.commit_group;" ::: "memory");
    load_tile(1, BK);
    asm volatile("cp.async.commit_group;" ::: "memory");
    load_tile(2, 2*BK);
    asm volatile("cp.async.commit_group;" ::: "memory");

    int rd = 0;
    for (int k0 = 0; k0 < K; k0 += BK) {
        asm volatile("cp.async.wait_group 2;" ::: "memory");
        __syncthreads();
        int kn = k0 + 3*BK;
        if (kn < K) {
            int ws = rd + 3; if (ws >= STAGES) ws -= STAGES;
            load_tile(ws, kn);
        }
        asm volatile("cp.async.commit_group;" ::: "memory");
        compute(rd);
        rd++; if (rd >= STAGES) rd = 0;
    }

    // ---- epilogue ----
    #pragma unroll
    for (int mi = 0; mi < 4; mi++) {
        int row0 = m0 + wm + mi*16 + g;
        int row1 = row0 + 8;
        float b0 = BIASROW ? biasR[row0] : 0.f;
        float b1 = BIASROW ? biasR[row1] : 0.f;
        float sum0 = 0.f, sum1 = 0.f;
        #pragma unroll
        for (int ni = 0; ni < 8; ni++) {
            int col = n0 + wn + ni*8 + 2*tg;
            float c0 = acc[mi][ni][0]*alpha;
            float c1 = acc[mi][ni][1]*alpha;
            float c2 = acc[mi][ni][2]*alpha;
            float c3 = acc[mi][ni][3]*alpha;
            if (SCORES) {
                c0 = __expf(c0); c1 = __expf(c1);
                c2 = __expf(c2); c3 = __expf(c3);
                sum0 += c0 + c1;
                sum1 += c2 + c3;
            }
            if (COLSCALE) {
                float i0 = __fdividef(1.f, colsum[col]);
                float i1 = __fdividef(1.f, colsum[col + 1]);
                c0 *= i0; c1 *= i1; c2 *= i0; c3 *= i1;
            }
            if (BIASCOL) {
                c0 += biasC[col]; c1 += biasC[col + 1];
                c2 += biasC[col]; c3 += biasC[col + 1];
            }
            c0 += b0; c1 += b0; c2 += b1; c3 += b1;
            if (RESID) {
                c0 += res[(size_t)row0*ldc + col];
                c1 += res[(size_t)row0*ldc + col + 1];
                c2 += res[(size_t)row1*ldc + col];
                c3 += res[(size_t)row1*ldc + col + 1];
            }
            if (OUTHALF) {
                __half* Ch = (__half*)Cv;
                *(__half2*)(Ch + (size_t)row0*ldc + col) = __floats2half2_rn(c0, c1);
                *(__half2*)(Ch + (size_t)row1*ldc + col) = __floats2half2_rn(c2, c3);
            } else {
                float* Cf = (float*)Cv;
                *(float2*)(Cf + (size_t)row0*ldc + col) = make_float2(c0, c1);
                *(float2*)(Cf + (size_t)row1*ldc + col) = make_float2(c2, c3);
            }
        }
        if (SCORES) {
            sum0 += __shfl_xor_sync(0xffffffffu, sum0, 1);
            sum0 += __shfl_xor_sync(0xffffffffu, sum0, 2);
            sum1 += __shfl_xor_sync(0xffffffffu, sum1, 1);
            sum1 += __shfl_xor_sync(0xffffffffu, sum1, 2);
            if (tg == 0) {
                atomicAdd(rowsum + row0, sum0);
                atomicAdd(rowsum + row1, sum1);
            }
        }
    }
}

// ---------------- kernel wrappers ----------------
// q/k: qT[pix,co] = hnT · W^T + b[co].  grid (8, 32, BATCH): x = sel*4 + ntile
__global__ void __launch_bounds__(128, 2) qk_kernel(
    const float* __restrict__ bq, const float* __restrict__ bk)
{
    const int b = blockIdx.z;
    const int sel = blockIdx.x >> 2;       // 0=q, 1=k
    const int nt  = blockIdx.x & 3;
    gemm_core<false, true, false, false, false, true>(
        g_hnT + (size_t)b*NPIX*CH, g_wh + (size_t)sel*CH*CH,
        (sel ? g_kT : g_qT) + (size_t)b*NPIX*CH,
        nullptr, sel ? bk : bq, nullptr, nullptr, nullptr,
        CH, CH, 1.f, blockIdx.y*128, nt*128);
}

// v: v[co,pix] = W · hnT^T + bv[co].  grid (32, 4, BATCH)
__global__ void __launch_bounds__(128, 2) v_kernel(const float* __restrict__ bv)
{
    const int b = blockIdx.z;
    gemm_core<true, false, false, false, false, true>(
        g_wh + (size_t)2*CH*CH, g_hnT + (size_t)b*NPIX*CH,
        g_v + (size_t)b*CH*NPIX,
        bv, nullptr, nullptr, nullptr, nullptr,
        CH, NPIX, 1.f, blockIdx.y*128, blockIdx.x*128);
}

// scores: e[i,j] = exp(scale * qT·kT^T), rowsums.  grid (32, 32, BATCH)
__global__ void __launch_bounds__(128, 2) scores_kernel(float scale)
{
    const int b = blockIdx.z;
    gemm_core<false, false, false, true, false, true>(
        g_qT + (size_t)b*NPIX*CH, g_kT + (size_t)b*NPIX*CH,
        g_e + (size_t)b*NPIX*NPIX,
        nullptr, nullptr, nullptr, g_S + (size_t)b*NPIX, nullptr,
        CH, NPIX, scale, blockIdx.y*128, blockIdx.x*128);
}

// av: oT[i,c] = e · v^T.  grid (4, 32, BATCH), K = NPIX
__global__ void __launch_bounds__(128, 2) av_kernel()
{
    const int b = blockIdx.z;
    gemm_core<false, false, false, false, false, true>(
        g_e + (size_t)b*NPIX*NPIX, g_v + (size_t)b*CH*NPIX,
        g_oT + (size_t)b*NPIX*CH,
        nullptr, nullptr, nullptr, nullptr, nullptr,
        NPIX, CH, 1.f, blockIdx.y*128, blockIdx.x*128);
}

// outconv: out[co,i] = (wo·oT^T)/S[i] + bo[co] + x[co,i].  grid (32, 4, BATCH)
__global__ void __launch_bounds__(128, 2) outconv_kernel(
    const float* __restrict__ bo, const float* __restrict__ x,
    float* __restrict__ out)
{
    const int b = blockIdx.z;
    gemm_core<true, false, true, false, true, false>(
        g_wh + (size_t)3*CH*CH, g_oT + (size_t)b*NPIX*CH,
        out + (size_t)b*CH*NPIX,
        bo, nullptr, x + (size_t)b*CH*NPIX, nullptr, g_S + (size_t)b*NPIX,
        CH, NPIX, 1.f, blockIdx.y*128, blockIdx.x*128);
}

// ---------------- launch ----------------
extern "C" void kernel_launch(void* const* d_in, const int* in_sizes, int n_in,
                              void* d_out, int out_size)
{
    const float* x     = (const float*)d_in[0];
    const float* gamma = (const float*)d_in[1];
    const float* beta  = (const float*)d_in[2];
    const float* wq    = (const float*)d_in[3];
    const float* bq    = (const float*)d_in[4];
    const float* wk    = (const float*)d_in[5];
    const float* bk    = (const float*)d_in[6];
    const float* wv    = (const float*)d_in[7];
    const float* bv    = (const float*)d_in[8];
    const float* wo    = (const float*)d_in[9];
    const float* bo    = (const float*)d_in[10];
    float* out = (float*)d_out;

    cudaFuncSetAttribute(qk_kernel,     cudaFuncAttributeMaxDynamicSharedMemorySize, SMEM_BYTES);
    cudaFuncSetAttribute(v_kernel,      cudaFuncAttributeMaxDynamicSharedMemorySize, SMEM_BYTES);
    cudaFuncSetAttribute(scores_kernel, cudaFuncAttributeMaxDynamicSharedMemorySize, SMEM_BYTES);
    cudaFuncSetAttribute(av_kernel,     cudaFuncAttributeMaxDynamicSharedMemorySize, SMEM_BYTES);
    cudaFuncSetAttribute(outconv_kernel,cudaFuncAttributeMaxDynamicSharedMemorySize, SMEM_BYTES);

    const float scale = rsqrtf((float)CH);

    gn_stats_kernel<<<dim3(GROUPS, BATCH), 256>>>(x);
    cvt_w_kernel<<<(4*CH*CH + 1023)/1024, 1024>>>(wq, wk, wv, wo);
    zero_S_kernel<<<(BATCH*NPIX + 255)/256, 256>>>();
    tnorm_kernel<<<dim3(NPIX/32, CH/32, BATCH), dim3(32, 8)>>>(x, gamma, beta);

    qk_kernel<<<dim3(8, NPIX/128, BATCH), 128, SMEM_BYTES>>>(bq, bk);
    v_kernel<<<dim3(NPIX/128, CH/128, BATCH), 128, SMEM_BYTES>>>(bv);
    scores_kernel<<<dim3(NPIX/128, NPIX/128, BATCH), 128, SMEM_BYTES>>>(scale);
    av_kernel<<<dim3(CH/128, NPIX/128, BATCH), 128, SMEM_BYTES>>>();
    outconv_kernel<<<dim3(NPIX/128, CH/128, BATCH), 128, SMEM_BYTES>>>(bo, x, out);
}

// round 9
// speedup vs baseline: 1.8002x; 1.0321x over previous
#include <cuda_runtime.h>
#include <cuda_fp16.h>
#include <math.h>
#include <stdint.h>

#define BATCH  2
#define CH     512
#define NPIX   4096
#define GROUPS 32
#define CPG    16
#define EPS    1e-6f
#define NSTG   4         // pipeline stages
#define BK     32
#define PIT    40        // smem row pitch in halfs
#define PW     20        // pitch in 32-bit words
#define STG_HALFS (128*PIT)          // per operand per stage
#define STG_BYTES (STG_HALFS*2*2)    // A+B per stage = 20480 B
#define SMEM_BYTES (1024 + NSTG*STG_BYTES)

// ---------------- scratch (device globals; no allocation) ----------------
__device__ __align__(256) __half g_hnT[(size_t)BATCH*NPIX*CH];  // [pix][ch]
__device__ __align__(256) __half g_qT [(size_t)BATCH*NPIX*CH];  // [pix][ch]
__device__ __align__(256) __half g_kT [(size_t)BATCH*NPIX*CH];  // [pix][ch]
__device__ __align__(256) __half g_v  [(size_t)BATCH*CH*NPIX];  // [ch][pix]
__device__ __align__(256) __half g_e  [(size_t)BATCH*NPIX*NPIX];// [i][j]
__device__ __align__(256) __half g_oT [(size_t)BATCH*NPIX*CH];  // [i][ch]
__device__ __align__(256) __half g_wh [(size_t)4*CH*CH];        // wq|wk|wv|wo
__device__ float g_S  [(size_t)BATCH*NPIX];
__device__ float g_stat[(size_t)BATCH*GROUPS*2];

// ---------------- GroupNorm stats ----------------
__global__ void gn_stats_kernel(const float* __restrict__ x)
{
    const int b = blockIdx.y, g = blockIdx.x;
    const size_t base = ((size_t)b*CH + (size_t)g*CPG) * NPIX;
    const float* xp = x + base;
    const int NE = CPG * NPIX;

    float s = 0.f, ss = 0.f;
    for (int i = threadIdx.x*4; i < NE; i += blockDim.x*4) {
        float4 v = *(const float4*)(xp + i);
        s  += v.x + v.y + v.z + v.w;
        ss += v.x*v.x + v.y*v.y + v.z*v.z + v.w*v.w;
    }
    __shared__ float sh1[256], sh2[256];
    sh1[threadIdx.x] = s; sh2[threadIdx.x] = ss;
    __syncthreads();
    for (int o = 128; o > 0; o >>= 1) {
        if (threadIdx.x < o) {
            sh1[threadIdx.x] += sh1[threadIdx.x + o];
            sh2[threadIdx.x] += sh2[threadIdx.x + o];
        }
        __syncthreads();
    }
    if (threadIdx.x == 0) {
        float mu  = sh1[0] / (float)NE;
        float var = sh2[0] / (float)NE - mu*mu;
        g_stat[(b*GROUPS + g)*2 + 0] = mu;
        g_stat[(b*GROUPS + g)*2 + 1] = rsqrtf(var + EPS);
    }
}

// ---------------- transpose + normalize -> hnT fp16 [pix][ch] ----------------
__global__ void tnorm_kernel(const float* __restrict__ x,
                             const float* __restrict__ gamma,
                             const float* __restrict__ beta)
{
    __shared__ float t[32][33];
    const int p0 = blockIdx.x*32, c0 = blockIdx.y*32, b = blockIdx.z;
    const float* xb = x + (size_t)b*CH*NPIX;
    __half* hb = g_hnT + (size_t)b*NPIX*CH;

    #pragma unroll
    for (int r = 0; r < 4; r++) {
        int c = c0 + threadIdx.y + r*8;
        float mu  = g_stat[(b*GROUPS + (c>>4))*2 + 0];
        float inv = g_stat[(b*GROUPS + (c>>4))*2 + 1];
        float v = xb[(size_t)c*NPIX + p0 + threadIdx.x];
        t[threadIdx.y + r*8][threadIdx.x] = (v - mu)*inv*gamma[c] + beta[c];
    }
    __syncthreads();
    #pragma unroll
    for (int r = 0; r < 4; r++) {
        int p = p0 + threadIdx.y + r*8;
        hb[(size_t)p*CH + c0 + threadIdx.x] = __float2half(t[threadIdx.x][threadIdx.y + r*8]);
    }
}

__global__ void cvt_w_kernel(const float* __restrict__ wq, const float* __restrict__ wk,
                             const float* __restrict__ wv, const float* __restrict__ wo)
{
    int i = blockIdx.x * blockDim.x + threadIdx.x;
    const int per = CH*CH;
    if (i >= 4*per) return;
    int m = i / per, off = i - m*per;
    const float* s = (m == 0) ? wq : (m == 1) ? wk : (m == 2) ? wv : wo;
    g_wh[i] = __float2half(s[off]);
}

__global__ void zero_S_kernel()
{
    int i = blockIdx.x * blockDim.x + threadIdx.x;
    if (i < BATCH*NPIX) g_S[i] = 0.f;
}

// ---------------- low-level helpers ----------------
__device__ __forceinline__ uint32_t smem_u32(const void* p) {
    return (uint32_t)__cvta_generic_to_shared(p);
}
__device__ __forceinline__ void cp16(uint32_t dst, const __half* src) {
    asm volatile("cp.async.cg.shared.global [%0], [%1], 16;" :: "r"(dst), "l"(src));
}
__device__ __forceinline__ void mbar_init(uint32_t a, uint32_t cnt) {
    asm volatile("mbarrier.init.shared.b64 [%0], %1;" :: "r"(a), "r"(cnt) : "memory");
}
__device__ __forceinline__ void mbar_arrive(uint32_t a) {
    asm volatile("mbarrier.arrive.shared.b64 _, [%0];" :: "r"(a) : "memory");
}
__device__ __forceinline__ void mbar_wait(uint32_t a, uint32_t parity) {
    asm volatile(
        "{\n\t.reg .pred P;\n\t"
        "LW_%=:\n\t"
        "mbarrier.try_wait.parity.acquire.cta.shared::cta.b64 P, [%0], %1, 0x989680;\n\t"
        "@P bra LD_%=;\n\t"
        "bra LW_%=;\n\t"
        "LD_%=:\n\t}"
        :: "r"(a), "r"(parity) : "memory");
}
__device__ __forceinline__ void mma_f16(float* c, const uint32_t* a, const uint32_t* b) {
    asm volatile(
        "mma.sync.aligned.m16n8k16.row.col.f32.f16.f16.f32 "
        "{%0,%1,%2,%3}, {%4,%5,%6,%7}, {%8,%9}, {%0,%1,%2,%3};"
        : "+f"(c[0]), "+f"(c[1]), "+f"(c[2]), "+f"(c[3])
        : "r"(a[0]), "r"(a[1]), "r"(a[2]), "r"(a[3]),
          "r"(b[0]), "r"(b[1]));
}

// ---------------- warp-specialized fp16 GEMM core ----------------
// C[m,n] = alpha * sum_k A[m,k]*B[n,k]; A [M][K] halfs, B [N][K] halfs.
// 160 threads: warps 0-3 consumers (64x64 each, 2x2 over 128x128 tile),
// warp 4 producer (all cp.async). 4-stage mbarrier ring, no __syncthreads
// in the mainloop.
template<bool BIASROW, bool BIASCOL, bool RESID, bool SCORES, bool COLSCALE, bool OUTHALF>
__device__ __forceinline__ void gemm_core(
    const __half* __restrict__ A, const __half* __restrict__ B,
    void* __restrict__ Cv,
    const float* __restrict__ biasR, const float* __restrict__ biasC,
    const float* __restrict__ res,
    float* __restrict__ rowsum, const float* __restrict__ colsum,
    int K, int ldc, float alpha, int m0, int n0)
{
    extern __shared__ __align__(16) char smem_raw[];
    const uint32_t sb = smem_u32(smem_raw);
    __half* data = (__half*)(smem_raw + 1024);

    const int tid  = threadIdx.x;
    const int lane = tid & 31;
    const int warp = tid >> 5;

    // barriers: full[s] at sb + s*8, empty[s] at sb + 32 + s*8
    if (tid == 0) {
        #pragma unroll
        for (int s = 0; s < NSTG; s++) {
            mbar_init(sb + s*8, 32);        // full: 32 producer arrivals
            mbar_init(sb + 32 + s*8, 128);  // empty: 128 consumer arrivals
        }
    }
    __syncthreads();

    const int T = K / BK;

    if (warp == 4) {
        // ---------------- producer ----------------
        for (int t = 0; t < T; t++) {
            const int s = t & (NSTG-1);
            if (t >= NSTG) {
                mbar_wait(sb + 32 + s*8, ((t - NSTG) >> 2) & 1);
            }
            __half* Ab = data + s*(2*STG_HALFS);
            __half* Bb = Ab + STG_HALFS;
            const int k0 = t * BK;
            #pragma unroll
            for (int i = 0; i < 16; i++) {
                int idx = lane + i*32;           // 0..511
                int row = idx >> 2, seg = (idx & 3) * 8;
                cp16(smem_u32(Ab + row*PIT + seg), A + (size_t)(m0 + row)*K + k0 + seg);
            }
            #pragma unroll
            for (int i = 0; i < 16; i++) {
                int idx = lane + i*32;
                int row = idx >> 2, seg = (idx & 3) * 8;
                cp16(smem_u32(Bb + row*PIT + seg), B + (size_t)(n0 + row)*K + k0 + seg);
            }
            asm volatile("cp.async.commit_group;" ::: "memory");
            if (t >= 3) {
                asm volatile("cp.async.wait_group 3;" ::: "memory");
                mbar_arrive(sb + ((t - 3) & (NSTG-1))*8);
            }
        }
        asm volatile("cp.async.wait_group 2;" ::: "memory");
        mbar_arrive(sb + ((T - 3) & (NSTG-1))*8);
        asm volatile("cp.async.wait_group 1;" ::: "memory");
        mbar_arrive(sb + ((T - 2) & (NSTG-1))*8);
        asm volatile("cp.async.wait_group 0;" ::: "memory");
        mbar_arrive(sb + ((T - 1) & (NSTG-1))*8);
        return;
    }

    // ---------------- consumers (warps 0-3) ----------------
    const int wm = (warp & 1) * 64;
    const int wn = (warp >> 1) * 64;
    const int g  = lane >> 2;
    const int tg = lane & 3;

    float acc[4][8][4];
    #pragma unroll
    for (int i = 0; i < 4; i++)
        #pragma unroll
        for (int j = 0; j < 8; j++)
            #pragma unroll
            for (int r = 0; r < 4; r++) acc[i][j][r] = 0.f;

    for (int t = 0; t < T; t++) {
        const int s = t & (NSTG-1);
        mbar_wait(sb + s*8, (t >> 2) & 1);

        const uint32_t* Aw = (const uint32_t*)(data + s*(2*STG_HALFS));
        const uint32_t* Bw = Aw + STG_HALFS/2;
        #pragma unroll
        for (int kk2 = 0; kk2 < 2; kk2++) {
            const int base = kk2*8 + tg;
            uint32_t af[4][4];
            #pragma unroll
            for (int mi = 0; mi < 4; mi++) {
                int r = wm + mi*16 + g;
                af[mi][0] = Aw[(r    )*PW + base];
                af[mi][1] = Aw[(r + 8)*PW + base];
                af[mi][2] = Aw[(r    )*PW + base + 4];
                af[mi][3] = Aw[(r + 8)*PW + base + 4];
            }
            #pragma unroll
            for (int ni = 0; ni < 8; ni++) {
                int cl = wn + ni*8 + g;
                uint32_t bf[2];
                bf[0] = Bw[cl*PW + base];
                bf[1] = Bw[cl*PW + base + 4];
                #pragma unroll
                for (int mi = 0; mi < 4; mi++)
                    mma_f16(acc[mi][ni], af[mi], bf);
            }
        }
        mbar_arrive(sb + 32 + s*8);
    }

    // ---- epilogue ----
    #pragma unroll
    for (int mi = 0; mi < 4; mi++) {
        int row0 = m0 + wm + mi*16 + g;
        int row1 = row0 + 8;
        float b0 = BIASROW ? biasR[row0] : 0.f;
        float b1 = BIASROW ? biasR[row1] : 0.f;
        float sum0 = 0.f, sum1 = 0.f;
        #pragma unroll
        for (int ni = 0; ni < 8; ni++) {
            int col = n0 + wn + ni*8 + 2*tg;
            float c0 = acc[mi][ni][0]*alpha;
            float c1 = acc[mi][ni][1]*alpha;
            float c2 = acc[mi][ni][2]*alpha;
            float c3 = acc[mi][ni][3]*alpha;
            if (SCORES) {
                c0 = __expf(c0); c1 = __expf(c1);
                c2 = __expf(c2); c3 = __expf(c3);
                sum0 += c0 + c1;
                sum1 += c2 + c3;
            }
            if (COLSCALE) {
                float i0 = __fdividef(1.f, colsum[col]);
                float i1 = __fdividef(1.f, colsum[col + 1]);
                c0 *= i0; c1 *= i1; c2 *= i0; c3 *= i1;
            }
            if (BIASCOL) {
                c0 += biasC[col]; c1 += biasC[col + 1];
                c2 += biasC[col]; c3 += biasC[col + 1];
            }
            c0 += b0; c1 += b0; c2 += b1; c3 += b1;
            if (RESID) {
                c0 += res[(size_t)row0*ldc + col];
                c1 += res[(size_t)row0*ldc + col + 1];
                c2 += res[(size_t)row1*ldc + col];
                c3 += res[(size_t)row1*ldc + col + 1];
            }
            if (OUTHALF) {
                __half* Ch = (__half*)Cv;
                *(__half2*)(Ch + (size_t)row0*ldc + col) = __floats2half2_rn(c0, c1);
                *(__half2*)(Ch + (size_t)row1*ldc + col) = __floats2half2_rn(c2, c3);
            } else {
                float* Cf = (float*)Cv;
                *(float2*)(Cf + (size_t)row0*ldc + col) = make_float2(c0, c1);
                *(float2*)(Cf + (size_t)row1*ldc + col) = make_float2(c2, c3);
            }
        }
        if (SCORES) {
            sum0 += __shfl_xor_sync(0xffffffffu, sum0, 1);
            sum0 += __shfl_xor_sync(0xffffffffu, sum0, 2);
            sum1 += __shfl_xor_sync(0xffffffffu, sum1, 1);
            sum1 += __shfl_xor_sync(0xffffffffu, sum1, 2);
            if (tg == 0) {
                atomicAdd(rowsum + row0, sum0);
                atomicAdd(rowsum + row1, sum1);
            }
        }
    }
}

// ---------------- kernel wrappers ----------------
__global__ void __launch_bounds__(160, 2) qk_kernel(
    const float* __restrict__ bq, const float* __restrict__ bk)
{
    const int b = blockIdx.z;
    const int sel = blockIdx.x >> 2;       // 0=q, 1=k
    const int nt  = blockIdx.x & 3;
    gemm_core<false, true, false, false, false, true>(
        g_hnT + (size_t)b*NPIX*CH, g_wh + (size_t)sel*CH*CH,
        (sel ? g_kT : g_qT) + (size_t)b*NPIX*CH,
        nullptr, sel ? bk : bq, nullptr, nullptr, nullptr,
        CH, CH, 1.f, blockIdx.y*128, nt*128);
}

__global__ void __launch_bounds__(160, 2) v_kernel(const float* __restrict__ bv)
{
    const int b = blockIdx.z;
    gemm_core<true, false, false, false, false, true>(
        g_wh + (size_t)2*CH*CH, g_hnT + (size_t)b*NPIX*CH,
        g_v + (size_t)b*CH*NPIX,
        bv, nullptr, nullptr, nullptr, nullptr,
        CH, NPIX, 1.f, blockIdx.y*128, blockIdx.x*128);
}

__global__ void __launch_bounds__(160, 2) scores_kernel(float scale)
{
    const int b = blockIdx.z;
    gemm_core<false, false, false, true, false, true>(
        g_qT + (size_t)b*NPIX*CH, g_kT + (size_t)b*NPIX*CH,
        g_e + (size_t)b*NPIX*NPIX,
        nullptr, nullptr, nullptr, g_S + (size_t)b*NPIX, nullptr,
        CH, NPIX, scale, blockIdx.y*128, blockIdx.x*128);
}

__global__ void __launch_bounds__(160, 2) av_kernel()
{
    const int b = blockIdx.z;
    gemm_core<false, false, false, false, false, true>(
        g_e + (size_t)b*NPIX*NPIX, g_v + (size_t)b*CH*NPIX,
        g_oT + (size_t)b*NPIX*CH,
        nullptr, nullptr, nullptr, nullptr, nullptr,
        NPIX, CH, 1.f, blockIdx.y*128, blockIdx.x*128);
}

__global__ void __launch_bounds__(160, 2) outconv_kernel(
    const float* __restrict__ bo, const float* __restrict__ x,
    float* __restrict__ out)
{
    const int b = blockIdx.z;
    gemm_core<true, false, true, false, true, false>(
        g_wh + (size_t)3*CH*CH, g_oT + (size_t)b*NPIX*CH,
        out + (size_t)b*CH*NPIX,
        bo, nullptr, x + (size_t)b*CH*NPIX, nullptr, g_S + (size_t)b*NPIX,
        CH, NPIX, 1.f, blockIdx.y*128, blockIdx.x*128);
}

// ---------------- launch ----------------
extern "C" void kernel_launch(void* const* d_in, const int* in_sizes, int n_in,
                              void* d_out, int out_size)
{
    const float* x     = (const float*)d_in[0];
    const float* gamma = (const float*)d_in[1];
    const float* beta  = (const float*)d_in[2];
    const float* wq    = (const float*)d_in[3];
    const float* bq    = (const float*)d_in[4];
    const float* wk    = (const float*)d_in[5];
    const float* bk    = (const float*)d_in[6];
    const float* wv    = (const float*)d_in[7];
    const float* bv    = (const float*)d_in[8];
    const float* wo    = (const float*)d_in[9];
    const float* bo    = (const float*)d_in[10];
    float* out = (float*)d_out;

    cudaFuncSetAttribute(qk_kernel,     cudaFuncAttributeMaxDynamicSharedMemorySize, SMEM_BYTES);
    cudaFuncSetAttribute(v_kernel,      cudaFuncAttributeMaxDynamicSharedMemorySize, SMEM_BYTES);
    cudaFuncSetAttribute(scores_kernel, cudaFuncAttributeMaxDynamicSharedMemorySize, SMEM_BYTES);
    cudaFuncSetAttribute(av_kernel,     cudaFuncAttributeMaxDynamicSharedMemorySize, SMEM_BYTES);
    cudaFuncSetAttribute(outconv_kernel,cudaFuncAttributeMaxDynamicSharedMemorySize, SMEM_BYTES);

    const float scale = rsqrtf((float)CH);

    gn_stats_kernel<<<dim3(GROUPS, BATCH), 256>>>(x);
    cvt_w_kernel<<<(4*CH*CH + 1023)/1024, 1024>>>(wq, wk, wv, wo);
    zero_S_kernel<<<(BATCH*NPIX + 255)/256, 256>>>();
    tnorm_kernel<<<dim3(NPIX/32, CH/32, BATCH), dim3(32, 8)>>>(x, gamma, beta);

    qk_kernel<<<dim3(8, NPIX/128, BATCH), 160, SMEM_BYTES>>>(bq, bk);
    v_kernel<<<dim3(NPIX/128, CH/128, BATCH), 160, SMEM_BYTES>>>(bv);
    scores_kernel<<<dim3(NPIX/128, NPIX/128, BATCH), 160, SMEM_BYTES>>>(scale);
    av_kernel<<<dim3(CH/128, NPIX/128, BATCH), 160, SMEM_BYTES>>>();
    outconv_kernel<<<dim3(NPIX/128, CH/128, BATCH), 160, SMEM_BYTES>>>(bo, x, out);
}

// round 10
// speedup vs baseline: 1.8240x; 1.0132x over previous
#include <cuda_runtime.h>
#include <cuda_fp16.h>
#include <math.h>
#include <stdint.h>

#define BATCH  2
#define CH     512
#define NPIX   4096
#define GROUPS 32
#define CPG    16
#define EPS    1e-6f
#define NSTG   4         // pipeline stages
#define BK     32
#define PIT    40        // smem row pitch in halfs
#define STG_HALFS (128*PIT)          // per operand per stage
#define STG_BYTES (STG_HALFS*2*2)    // A+B per stage = 20480 B
#define SMEM_BYTES (1024 + NSTG*STG_BYTES)

// ---------------- scratch (device globals; no allocation) ----------------
__device__ __align__(256) __half g_hnT[(size_t)BATCH*NPIX*CH];  // [pix][ch]
__device__ __align__(256) __half g_qT [(size_t)BATCH*NPIX*CH];  // [pix][ch]
__device__ __align__(256) __half g_kT [(size_t)BATCH*NPIX*CH];  // [pix][ch]
__device__ __align__(256) __half g_v  [(size_t)BATCH*CH*NPIX];  // [ch][pix]
__device__ __align__(256) __half g_e  [(size_t)BATCH*NPIX*NPIX];// [i][j]
__device__ __align__(256) __half g_oT [(size_t)BATCH*NPIX*CH];  // [i][ch]
__device__ __align__(256) __half g_wh [(size_t)4*CH*CH];        // wq|wk|wv|wo
__device__ float g_S  [(size_t)BATCH*NPIX];
__device__ float g_stat[(size_t)BATCH*GROUPS*2];

// ---------------- GroupNorm stats ----------------
__global__ void gn_stats_kernel(const float* __restrict__ x)
{
    const int b = blockIdx.y, g = blockIdx.x;
    const size_t base = ((size_t)b*CH + (size_t)g*CPG) * NPIX;
    const float* xp = x + base;
    const int NE = CPG * NPIX;

    float s = 0.f, ss = 0.f;
    for (int i = threadIdx.x*4; i < NE; i += blockDim.x*4) {
        float4 v = *(const float4*)(xp + i);
        s  += v.x + v.y + v.z + v.w;
        ss += v.x*v.x + v.y*v.y + v.z*v.z + v.w*v.w;
    }
    __shared__ float sh1[256], sh2[256];
    sh1[threadIdx.x] = s; sh2[threadIdx.x] = ss;
    __syncthreads();
    for (int o = 128; o > 0; o >>= 1) {
        if (threadIdx.x < o) {
            sh1[threadIdx.x] += sh1[threadIdx.x + o];
            sh2[threadIdx.x] += sh2[threadIdx.x + o];
        }
        __syncthreads();
    }
    if (threadIdx.x == 0) {
        float mu  = sh1[0] / (float)NE;
        float var = sh2[0] / (float)NE - mu*mu;
        g_stat[(b*GROUPS + g)*2 + 0] = mu;
        g_stat[(b*GROUPS + g)*2 + 1] = rsqrtf(var + EPS);
    }
}

// ---------------- transpose + normalize -> hnT fp16 [pix][ch] ----------------
__global__ void tnorm_kernel(const float* __restrict__ x,
                             const float* __restrict__ gamma,
                             const float* __restrict__ beta)
{
    __shared__ float t[32][33];
    const int p0 = blockIdx.x*32, c0 = blockIdx.y*32, b = blockIdx.z;
    const float* xb = x + (size_t)b*CH*NPIX;
    __half* hb = g_hnT + (size_t)b*NPIX*CH;

    #pragma unroll
    for (int r = 0; r < 4; r++) {
        int c = c0 + threadIdx.y + r*8;
        float mu  = g_stat[(b*GROUPS + (c>>4))*2 + 0];
        float inv = g_stat[(b*GROUPS + (c>>4))*2 + 1];
        float v = xb[(size_t)c*NPIX + p0 + threadIdx.x];
        t[threadIdx.y + r*8][threadIdx.x] = (v - mu)*inv*gamma[c] + beta[c];
    }
    __syncthreads();
    #pragma unroll
    for (int r = 0; r < 4; r++) {
        int p = p0 + threadIdx.y + r*8;
        hb[(size_t)p*CH + c0 + threadIdx.x] = __float2half(t[threadIdx.x][threadIdx.y + r*8]);
    }
}

__global__ void cvt_w_kernel(const float* __restrict__ wq, const float* __restrict__ wk,
                             const float* __restrict__ wv, const float* __restrict__ wo)
{
    int i = blockIdx.x * blockDim.x + threadIdx.x;
    const int per = CH*CH;
    if (i >= 4*per) return;
    int m = i / per, off = i - m*per;
    const float* s = (m == 0) ? wq : (m == 1) ? wk : (m == 2) ? wv : wo;
    g_wh[i] = __float2half(s[off]);
}

__global__ void zero_S_kernel()
{
    int i = blockIdx.x * blockDim.x + threadIdx.x;
    if (i < BATCH*NPIX) g_S[i] = 0.f;
}

// ---------------- low-level helpers ----------------
__device__ __forceinline__ uint32_t smem_u32(const void* p) {
    return (uint32_t)__cvta_generic_to_shared(p);
}
__device__ __forceinline__ void cp16(uint32_t dst, const __half* src) {
    asm volatile("cp.async.cg.shared.global [%0], [%1], 16;" :: "r"(dst), "l"(src));
}
__device__ __forceinline__ void mbar_init(uint32_t a, uint32_t cnt) {
    asm volatile("mbarrier.init.shared.b64 [%0], %1;" :: "r"(a), "r"(cnt) : "memory");
}
__device__ __forceinline__ void mbar_arrive(uint32_t a) {
    asm volatile("mbarrier.arrive.shared.b64 _, [%0];" :: "r"(a) : "memory");
}
__device__ __forceinline__ void mbar_wait(uint32_t a, uint32_t parity) {
    asm volatile(
        "{\n\t.reg .pred P;\n\t"
        "LW_%=:\n\t"
        "mbarrier.try_wait.parity.acquire.cta.shared::cta.b64 P, [%0], %1, 0x989680;\n\t"
        "@P bra LD_%=;\n\t"
        "bra LW_%=;\n\t"
        "LD_%=:\n\t}"
        :: "r"(a), "r"(parity) : "memory");
}
__device__ __forceinline__ void mma_f16(float* c, const uint32_t* a, const uint32_t* b) {
    asm volatile(
        "mma.sync.aligned.m16n8k16.row.col.f32.f16.f16.f32 "
        "{%0,%1,%2,%3}, {%4,%5,%6,%7}, {%8,%9}, {%0,%1,%2,%3};"
        : "+f"(c[0]), "+f"(c[1]), "+f"(c[2]), "+f"(c[3])
        : "r"(a[0]), "r"(a[1]), "r"(a[2]), "r"(a[3]),
          "r"(b[0]), "r"(b[1]));
}
__device__ __forceinline__ void ldsm4(uint32_t* r, uint32_t addr) {
    asm volatile("ldmatrix.sync.aligned.m8n8.x4.shared.b16 {%0,%1,%2,%3}, [%4];"
                 : "=r"(r[0]), "=r"(r[1]), "=r"(r[2]), "=r"(r[3]) : "r"(addr));
}

// ---------------- warp-specialized fp16 GEMM core ----------------
// C[m,n] = alpha * sum_k A[m,k]*B[n,k]; A [M][K] halfs, B [N][K] halfs.
// 160 threads: warps 0-3 consumers (64x64 each, 2x2 over 128x128 tile),
// warp 4 producer. 4-stage mbarrier ring. Fragments via ldmatrix.x4
// (pitch 40 halfs -> 8-row LDSM phases hit disjoint bank sets).
template<bool BIASROW, bool BIASCOL, bool RESID, bool SCORES, bool COLSCALE, bool OUTHALF>
__device__ __forceinline__ void gemm_core(
    const __half* __restrict__ A, const __half* __restrict__ B,
    void* __restrict__ Cv,
    const float* __restrict__ biasR, const float* __restrict__ biasC,
    const float* __restrict__ res,
    float* __restrict__ rowsum, const float* __restrict__ colsum,
    int K, int ldc, float alpha, int m0, int n0)
{
    extern __shared__ __align__(16) char smem_raw[];
    const uint32_t sb = smem_u32(smem_raw);
    __half* data = (__half*)(smem_raw + 1024);

    const int tid  = threadIdx.x;
    const int lane = tid & 31;
    const int warp = tid >> 5;

    // barriers: full[s] at sb + s*8, empty[s] at sb + 32 + s*8
    if (tid == 0) {
        #pragma unroll
        for (int s = 0; s < NSTG; s++) {
            mbar_init(sb + s*8, 32);        // full: 32 producer arrivals
            mbar_init(sb + 32 + s*8, 128);  // empty: 128 consumer arrivals
        }
    }
    __syncthreads();

    const int T = K / BK;

    if (warp == 4) {
        // ---------------- producer ----------------
        for (int t = 0; t < T; t++) {
            const int s = t & (NSTG-1);
            if (t >= NSTG) {
                mbar_wait(sb + 32 + s*8, ((t - NSTG) >> 2) & 1);
            }
            __half* Ab = data + s*(2*STG_HALFS);
            __half* Bb = Ab + STG_HALFS;
            const int k0 = t * BK;
            #pragma unroll
            for (int i = 0; i < 16; i++) {
                int idx = lane + i*32;           // 0..511
                int row = idx >> 2, seg = (idx & 3) * 8;
                cp16(smem_u32(Ab + row*PIT + seg), A + (size_t)(m0 + row)*K + k0 + seg);
            }
            #pragma unroll
            for (int i = 0; i < 16; i++) {
                int idx = lane + i*32;
                int row = idx >> 2, seg = (idx & 3) * 8;
                cp16(smem_u32(Bb + row*PIT + seg), B + (size_t)(n0 + row)*K + k0 + seg);
            }
            asm volatile("cp.async.commit_group;" ::: "memory");
            if (t >= 3) {
                asm volatile("cp.async.wait_group 3;" ::: "memory");
                mbar_arrive(sb + ((t - 3) & (NSTG-1))*8);
            }
        }
        asm volatile("cp.async.wait_group 2;" ::: "memory");
        mbar_arrive(sb + ((T - 3) & (NSTG-1))*8);
        asm volatile("cp.async.wait_group 1;" ::: "memory");
        mbar_arrive(sb + ((T - 2) & (NSTG-1))*8);
        asm volatile("cp.async.wait_group 0;" ::: "memory");
        mbar_arrive(sb + ((T - 1) & (NSTG-1))*8);
        return;
    }

    // ---------------- consumers (warps 0-3) ----------------
    const int wm = (warp & 1) * 64;
    const int wn = (warp >> 1) * 64;
    const int g  = lane >> 2;
    const int tg = lane & 3;

    // LDSM lane geometry
    const int a_r = (lane & 7) + ((lane >> 3) & 1) * 8;  // row within 16
    const int a_k = (lane >> 4) * 8;                     // k offset (halfs)
    const int b_n = ((lane >> 4) * 8) + (lane & 7);      // n within 16 (mat pair)
    const int b_k = ((lane >> 3) & 1) * 8;               // k offset (halfs)

    float acc[4][8][4];
    #pragma unroll
    for (int i = 0; i < 4; i++)
        #pragma unroll
        for (int j = 0; j < 8; j++)
            #pragma unroll
            for (int r = 0; r < 4; r++) acc[i][j][r] = 0.f;

    for (int t = 0; t < T; t++) {
        const int s = t & (NSTG-1);
        mbar_wait(sb + s*8, (t >> 2) & 1);

        const __half* Ah = data + s*(2*STG_HALFS);
        const __half* Bh = Ah + STG_HALFS;
        #pragma unroll
        for (int kk2 = 0; kk2 < 2; kk2++) {
            uint32_t af[4][4];
            #pragma unroll
            for (int mi = 0; mi < 4; mi++)
                ldsm4(af[mi], smem_u32(Ah + (wm + mi*16 + a_r)*PIT + kk2*16 + a_k));
            uint32_t bf[8][2];
            #pragma unroll
            for (int p = 0; p < 4; p++) {
                uint32_t r[4];
                ldsm4(r, smem_u32(Bh + (wn + p*16 + b_n)*PIT + kk2*16 + b_k));
                bf[2*p  ][0] = r[0]; bf[2*p  ][1] = r[1];
                bf[2*p+1][0] = r[2]; bf[2*p+1][1] = r[3];
            }
            #pragma unroll
            for (int ni = 0; ni < 8; ni++)
                #pragma unroll
                for (int mi = 0; mi < 4; mi++)
                    mma_f16(acc[mi][ni], af[mi], bf[ni]);
        }
        mbar_arrive(sb + 32 + s*8);
    }

    // ---- epilogue ----
    #pragma unroll
    for (int mi = 0; mi < 4; mi++) {
        int row0 = m0 + wm + mi*16 + g;
        int row1 = row0 + 8;
        float b0 = BIASROW ? biasR[row0] : 0.f;
        float b1 = BIASROW ? biasR[row1] : 0.f;
        float sum0 = 0.f, sum1 = 0.f;
        #pragma unroll
        for (int ni = 0; ni < 8; ni++) {
            int col = n0 + wn + ni*8 + 2*tg;
            float c0 = acc[mi][ni][0]*alpha;
            float c1 = acc[mi][ni][1]*alpha;
            float c2 = acc[mi][ni][2]*alpha;
            float c3 = acc[mi][ni][3]*alpha;
            if (SCORES) {
                c0 = __expf(c0); c1 = __expf(c1);
                c2 = __expf(c2); c3 = __expf(c3);
                sum0 += c0 + c1;
                sum1 += c2 + c3;
            }
            if (COLSCALE) {
                float i0 = __fdividef(1.f, colsum[col]);
                float i1 = __fdividef(1.f, colsum[col + 1]);
                c0 *= i0; c1 *= i1; c2 *= i0; c3 *= i1;
            }
            if (BIASCOL) {
                c0 += biasC[col]; c1 += biasC[col + 1];
                c2 += biasC[col]; c3 += biasC[col + 1];
            }
            c0 += b0; c1 += b0; c2 += b1; c3 += b1;
            if (RESID) {
                c0 += res[(size_t)row0*ldc + col];
                c1 += res[(size_t)row0*ldc + col + 1];
                c2 += res[(size_t)row1*ldc + col];
                c3 += res[(size_t)row1*ldc + col + 1];
            }
            if (OUTHALF) {
                __half* Ch = (__half*)Cv;
                *(__half2*)(Ch + (size_t)row0*ldc + col) = __floats2half2_rn(c0, c1);
                *(__half2*)(Ch + (size_t)row1*ldc + col) = __floats2half2_rn(c2, c3);
            } else {
                float* Cf = (float*)Cv;
                *(float2*)(Cf + (size_t)row0*ldc + col) = make_float2(c0, c1);
                *(float2*)(Cf + (size_t)row1*ldc + col) = make_float2(c2, c3);
            }
        }
        if (SCORES) {
            sum0 += __shfl_xor_sync(0xffffffffu, sum0, 1);
            sum0 += __shfl_xor_sync(0xffffffffu, sum0, 2);
            sum1 += __shfl_xor_sync(0xffffffffu, sum1, 1);
            sum1 += __shfl_xor_sync(0xffffffffu, sum1, 2);
            if (tg == 0) {
                atomicAdd(rowsum + row0, sum0);
                atomicAdd(rowsum + row1, sum1);
            }
        }
    }
}

// ---------------- kernel wrappers ----------------
__global__ void __launch_bounds__(160, 2) qk_kernel(
    const float* __restrict__ bq, const float* __restrict__ bk)
{
    const int b = blockIdx.z;
    const int sel = blockIdx.x >> 2;       // 0=q, 1=k
    const int nt  = blockIdx.x & 3;
    gemm_core<false, true, false, false, false, true>(
        g_hnT + (size_t)b*NPIX*CH, g_wh + (size_t)sel*CH*CH,
        (sel ? g_kT : g_qT) + (size_t)b*NPIX*CH,
        nullptr, sel ? bk : bq, nullptr, nullptr, nullptr,
        CH, CH, 1.f, blockIdx.y*128, nt*128);
}

__global__ void __launch_bounds__(160, 2) v_kernel(const float* __restrict__ bv)
{
    const int b = blockIdx.z;
    gemm_core<true, false, false, false, false, true>(
        g_wh + (size_t)2*CH*CH, g_hnT + (size_t)b*NPIX*CH,
        g_v + (size_t)b*CH*NPIX,
        bv, nullptr, nullptr, nullptr, nullptr,
        CH, NPIX, 1.f, blockIdx.y*128, blockIdx.x*128);
}

__global__ void __launch_bounds__(160, 2) scores_kernel(float scale)
{
    const int b = blockIdx.z;
    gemm_core<false, false, false, true, false, true>(
        g_qT + (size_t)b*NPIX*CH, g_kT + (size_t)b*NPIX*CH,
        g_e + (size_t)b*NPIX*NPIX,
        nullptr, nullptr, nullptr, g_S + (size_t)b*NPIX, nullptr,
        CH, NPIX, scale, blockIdx.y*128, blockIdx.x*128);
}

__global__ void __launch_bounds__(160, 2) av_kernel()
{
    const int b = blockIdx.z;
    gemm_core<false, false, false, false, false, true>(
        g_e + (size_t)b*NPIX*NPIX, g_v + (size_t)b*CH*NPIX,
        g_oT + (size_t)b*NPIX*CH,
        nullptr, nullptr, nullptr, nullptr, nullptr,
        NPIX, CH, 1.f, blockIdx.y*128, blockIdx.x*128);
}

__global__ void __launch_bounds__(160, 2) outconv_kernel(
    const float* __restrict__ bo, const float* __restrict__ x,
    float* __restrict__ out)
{
    const int b = blockIdx.z;
    gemm_core<true, false, true, false, true, false>(
        g_wh + (size_t)3*CH*CH, g_oT + (size_t)b*NPIX*CH,
        out + (size_t)b*CH*NPIX,
        bo, nullptr, x + (size_t)b*CH*NPIX, nullptr, g_S + (size_t)b*NPIX,
        CH, NPIX, 1.f, blockIdx.y*128, blockIdx.x*128);
}

// ---------------- launch ----------------
extern "C" void kernel_launch(void* const* d_in, const int* in_sizes, int n_in,
                              void* d_out, int out_size)
{
    const float* x     = (const float*)d_in[0];
    const float* gamma = (const float*)d_in[1];
    const float* beta  = (const float*)d_in[2];
    const float* wq    = (const float*)d_in[3];
    const float* bq    = (const float*)d_in[4];
    const float* wk    = (const float*)d_in[5];
    const float* bk    = (const float*)d_in[6];
    const float* wv    = (const float*)d_in[7];
    const float* bv    = (const float*)d_in[8];
    const float* wo    = (const float*)d_in[9];
    const float* bo    = (const float*)d_in[10];
    float* out = (float*)d_out;

    cudaFuncSetAttribute(qk_kernel,     cudaFuncAttributeMaxDynamicSharedMemorySize, SMEM_BYTES);
    cudaFuncSetAttribute(v_kernel,      cudaFuncAttributeMaxDynamicSharedMemorySize, SMEM_BYTES);
    cudaFuncSetAttribute(scores_kernel, cudaFuncAttributeMaxDynamicSharedMemorySize, SMEM_BYTES);
    cudaFuncSetAttribute(av_kernel,     cudaFuncAttributeMaxDynamicSharedMemorySize, SMEM_BYTES);
    cudaFuncSetAttribute(outconv_kernel,cudaFuncAttributeMaxDynamicSharedMemorySize, SMEM_BYTES);

    const float scale = rsqrtf((float)CH);

    gn_stats_kernel<<<dim3(GROUPS, BATCH), 256>>>(x);
    cvt_w_kernel<<<(4*CH*CH + 1023)/1024, 1024>>>(wq, wk, wv, wo);
    zero_S_kernel<<<(BATCH*NPIX + 255)/256, 256>>>();
    tnorm_kernel<<<dim3(NPIX/32, CH/32, BATCH), dim3(32, 8)>>>(x, gamma, beta);

    qk_kernel<<<dim3(8, NPIX/128, BATCH), 160, SMEM_BYTES>>>(bq, bk);
    v_kernel<<<dim3(NPIX/128, CH/128, BATCH), 160, SMEM_BYTES>>>(bv);
    scores_kernel<<<dim3(NPIX/128, NPIX/128, BATCH), 160, SMEM_BYTES>>>(scale);
    av_kernel<<<dim3(CH/128, NPIX/128, BATCH), 160, SMEM_BYTES>>>();
    outconv_kernel<<<dim3(NPIX/128, CH/128, BATCH), 160, SMEM_BYTES>>>(bo, x, out);
}